// round 1
// baseline (speedup 1.0000x reference)
#include <cuda_runtime.h>
#include <math.h>

// Problem constants
#define BB 2
#define SS 2048
#define DD 2048
#define HH 16
#define HD 128
#define BS (BB * SS)        // 4096 tokens
#define NPAIR (HD / 2)      // 64 rope pairs per head

// ---------------------------------------------------------------------------
// Scratch (device globals -- no allocation allowed in kernel_launch)
// ---------------------------------------------------------------------------
__device__ float g_q[BS * DD];
__device__ float g_k[BS * DD];
__device__ float g_v[BS * DD];
__device__ float g_ao[BS * DD];
__device__ float g_cos[SS * NPAIR];
__device__ float g_sin[SS * NPAIR];

// ---------------------------------------------------------------------------
// RoPE table: cos/sin computed in double for accuracy, stored fp32
// ---------------------------------------------------------------------------
__global__ void rope_table_kernel() {
    int idx = blockIdx.x * blockDim.x + threadIdx.x;
    if (idx >= SS * NPAIR) return;
    int s = idx / NPAIR;
    int i = idx - s * NPAIR;
    double freq = (double)s * exp(((double)(-2 * i) / (double)HD) * log(10000.0));
    g_cos[idx] = (float)cos(freq);
    g_sin[idx] = (float)sin(freq);
}

// ---------------------------------------------------------------------------
// Apply RoPE in place to g_q and g_k.
// Within a token, pair p (0..1023) lives at element offset 2p
// (since h*128 + 2*(p%64) == 2p when h = p/64).
// ---------------------------------------------------------------------------
__global__ void rope_apply_kernel() {
    int idx = blockIdx.x * blockDim.x + threadIdx.x;
    if (idx >= BS * (DD / 2)) return;
    int t = idx >> 10;            // token index (D/2 = 1024 pairs per token)
    int p = idx & 1023;
    int i = p & (NPAIR - 1);
    int s = t & (SS - 1);
    float c  = g_cos[(s << 6) + i];
    float sn = g_sin[(s << 6) + i];
    size_t base = ((size_t)t << 11) + ((size_t)p << 1);
    float2 q2 = *reinterpret_cast<float2*>(&g_q[base]);
    float2 k2 = *reinterpret_cast<float2*>(&g_k[base]);
    float2 qo = make_float2(q2.x * c - q2.y * sn, q2.x * sn + q2.y * c);
    float2 ko = make_float2(k2.x * c - k2.y * sn, k2.x * sn + k2.y * c);
    *reinterpret_cast<float2*>(&g_q[base]) = qo;
    *reinterpret_cast<float2*>(&g_k[base]) = ko;
}

// ---------------------------------------------------------------------------
// SGEMM: C[M,N] = A[M,K] * B[N,K]^T   (both row-major; B is a weight [N,K])
// 128x128 block tile, BK=8, 8x8 per-thread microtile, 256 threads.
// M % 128 == 0, N % 128 == 0, K % 8 == 0 (holds: 4096/2048/2048).
// ---------------------------------------------------------------------------
__global__ __launch_bounds__(256) void sgemm_nt(
    const float* __restrict__ A, const float* __restrict__ Bw,
    float* __restrict__ C, int M, int N, int K)
{
    __shared__ float As[8][128];
    __shared__ float Bs[8][128];

    const int tid = threadIdx.x;
    const int bm = blockIdx.y * 128;
    const int bn = blockIdx.x * 128;

    const int lrow = tid >> 1;          // 0..127
    const int lcol = (tid & 1) << 2;    // 0 or 4
    const int ty = tid >> 4;            // 0..15
    const int tx = tid & 15;            // 0..15

    const float* Ag = A  + (size_t)(bm + lrow) * K + lcol;
    const float* Bg = Bw + (size_t)(bn + lrow) * K + lcol;

    float acc[8][8];
#pragma unroll
    for (int i = 0; i < 8; i++)
#pragma unroll
        for (int j = 0; j < 8; j++) acc[i][j] = 0.f;

    for (int k0 = 0; k0 < K; k0 += 8) {
        float4 av = *reinterpret_cast<const float4*>(Ag + k0);
        float4 bv = *reinterpret_cast<const float4*>(Bg + k0);
        As[lcol + 0][lrow] = av.x;
        As[lcol + 1][lrow] = av.y;
        As[lcol + 2][lrow] = av.z;
        As[lcol + 3][lrow] = av.w;
        Bs[lcol + 0][lrow] = bv.x;
        Bs[lcol + 1][lrow] = bv.y;
        Bs[lcol + 2][lrow] = bv.z;
        Bs[lcol + 3][lrow] = bv.w;
        __syncthreads();

#pragma unroll
        for (int kk = 0; kk < 8; kk++) {
            float4 a0 = *reinterpret_cast<const float4*>(&As[kk][ty * 8]);
            float4 a1 = *reinterpret_cast<const float4*>(&As[kk][ty * 8 + 4]);
            float4 b0 = *reinterpret_cast<const float4*>(&Bs[kk][tx * 8]);
            float4 b1 = *reinterpret_cast<const float4*>(&Bs[kk][tx * 8 + 4]);
            float ar[8] = {a0.x, a0.y, a0.z, a0.w, a1.x, a1.y, a1.z, a1.w};
            float br[8] = {b0.x, b0.y, b0.z, b0.w, b1.x, b1.y, b1.z, b1.w};
#pragma unroll
            for (int i = 0; i < 8; i++)
#pragma unroll
                for (int j = 0; j < 8; j++)
                    acc[i][j] += ar[i] * br[j];
        }
        __syncthreads();
    }

#pragma unroll
    for (int i = 0; i < 8; i++) {
        size_t row = (size_t)(bm + ty * 8 + i) * N + bn + tx * 8;
        float4 v0 = make_float4(acc[i][0], acc[i][1], acc[i][2], acc[i][3]);
        float4 v1 = make_float4(acc[i][4], acc[i][5], acc[i][6], acc[i][7]);
        *reinterpret_cast<float4*>(&C[row])     = v0;
        *reinterpret_cast<float4*>(&C[row + 4]) = v1;
    }
}

// ---------------------------------------------------------------------------
// Flash attention: one block per (q-tile of 64, b*h). Online softmax.
// smem layout (floats):
//   Qt [128][65]  transposed Q tile (pad 65 -> conflict-free transpose store)
//   KV [128][65]  (as Kt[d][j]) or [64][128] (as Vs[j][d]) -- reused buffer
//   Pt [64][65]   scores/probs, TRANSPOSED: Pt[key][query]
//   m_s/l_s/al_s [64] running max / denom / rescale
// ---------------------------------------------------------------------------
#define FLASH_SMEM_FLOATS (2 * 128 * 65 + 64 * 65 + 3 * 64)
#define FLASH_SMEM_BYTES  (FLASH_SMEM_FLOATS * 4)

__global__ __launch_bounds__(256, 2) void flash_kernel() {
    extern __shared__ float sm[];
    float* Qt  = sm;                      // 128*65
    float* KV  = sm + 128 * 65;           // 128*65 (Kt) / 64*128 (Vs)
    float* Pt  = sm + 2 * 128 * 65;       // 64*65
    float* m_s  = Pt + 64 * 65;
    float* l_s  = m_s + 64;
    float* al_s = l_s + 64;

    const int tid = threadIdx.x;
    const int q0  = blockIdx.x * 64;
    const int bh  = blockIdx.y;
    const int b   = bh >> 4;
    const int h   = bh & 15;
    const size_t base_bh = (size_t)b * SS * DD + (size_t)h * HD;

    // Load Q tile transposed: Qt[d][r]. Conflict-free: addr = 65*d + r,
    // consecutive lanes vary d -> bank = d mod 32.
#pragma unroll
    for (int rep = 0; rep < 32; rep++) {
        int lin = rep * 256 + tid;
        int r = lin >> 7;
        int d = lin & 127;
        Qt[d * 65 + r] = g_q[base_bh + (size_t)(q0 + r) * DD + d];
    }

    if (tid < 64) { m_s[tid] = -INFINITY; l_s[tid] = 0.f; }

    float oacc[8][4];
#pragma unroll
    for (int a = 0; a < 8; a++)
#pragma unroll
        for (int c = 0; c < 4; c++) oacc[a][c] = 0.f;

    const int ty = tid >> 4, tx = tid & 15;   // scores: rows 4*ty.., cols 4*tx..
    const int ry = tid >> 5, cx = tid & 31;   // PV: rows 8*ry.., cols 4*cx..

    for (int kv0 = 0; kv0 < SS; kv0 += 64) {
        __syncthreads();  // previous PV done reading KV (Vs)

        // K tile transposed: Kt[d][j]
#pragma unroll
        for (int rep = 0; rep < 32; rep++) {
            int lin = rep * 256 + tid;
            int j = lin >> 7;
            int d = lin & 127;
            KV[d * 65 + j] = g_k[base_bh + (size_t)(kv0 + j) * DD + d];
        }
        __syncthreads();

        // Scores: S[r][c] = sum_d Qt[d][r] * Kt[d][c], scaled by 1/sqrt(128)
        float sacc[4][4];
#pragma unroll
        for (int a = 0; a < 4; a++)
#pragma unroll
            for (int c = 0; c < 4; c++) sacc[a][c] = 0.f;

#pragma unroll 4
        for (int d = 0; d < 128; d++) {
            float ar[4], br[4];
#pragma unroll
            for (int a = 0; a < 4; a++) ar[a] = Qt[d * 65 + 4 * ty + a];
#pragma unroll
            for (int c = 0; c < 4; c++) br[c] = KV[d * 65 + 4 * tx + c];
#pragma unroll
            for (int a = 0; a < 4; a++)
#pragma unroll
                for (int c = 0; c < 4; c++)
                    sacc[a][c] += ar[a] * br[c];
        }
#pragma unroll
        for (int c = 0; c < 4; c++)
#pragma unroll
            for (int a = 0; a < 4; a++)
                Pt[(4 * tx + c) * 65 + 4 * ty + a] =
                    sacc[a][c] * 0.08838834764831845f;
        __syncthreads();

        // Load V tile row-major into KV (all threads); conflict-free.
#pragma unroll
        for (int rep = 0; rep < 8; rep++) {
            int lin4 = rep * 256 + tid;
            int j  = lin4 >> 5;
            int d4 = (lin4 & 31) << 2;
            *reinterpret_cast<float4*>(&KV[j * 128 + d4]) =
                *reinterpret_cast<const float4*>(
                    &g_v[base_bh + (size_t)(kv0 + j) * DD + d4]);
        }

        // Online softmax bookkeeping (one thread per query row)
        if (tid < 64) {
            const int r = tid;
            float mi = m_s[r];
            float mx = mi;
#pragma unroll 8
            for (int c = 0; c < 64; c++)
                mx = fmaxf(mx, Pt[c * 65 + r]);
            float alpha = __expf(mi - mx);
            float sum = 0.f;
#pragma unroll 8
            for (int c = 0; c < 64; c++) {
                float p = __expf(Pt[c * 65 + r] - mx);
                Pt[c * 65 + r] = p;
                sum += p;
            }
            m_s[r]  = mx;
            l_s[r]  = l_s[r] * alpha + sum;
            al_s[r] = alpha;
        }
        __syncthreads();

        // O update: O[r][d] = O[r][d]*alpha[r] + sum_j P[r][j] * V[j][d]
        float al[8];
#pragma unroll
        for (int a = 0; a < 8; a++) al[a] = al_s[ry * 8 + a];
#pragma unroll
        for (int a = 0; a < 8; a++)
#pragma unroll
            for (int c = 0; c < 4; c++) oacc[a][c] *= al[a];

#pragma unroll 2
        for (int j = 0; j < 64; j++) {
            float4 vv = *reinterpret_cast<float4*>(&KV[j * 128 + 4 * cx]);
#pragma unroll
            for (int a = 0; a < 8; a++) {
                float p = Pt[j * 65 + ry * 8 + a];
                oacc[a][0] += p * vv.x;
                oacc[a][1] += p * vv.y;
                oacc[a][2] += p * vv.z;
                oacc[a][3] += p * vv.w;
            }
        }
    }

    // Normalize and write out to g_ao ([B,S,H,hd] layout == [BS, D])
#pragma unroll
    for (int a = 0; a < 8; a++) {
        float inv = 1.0f / l_s[ry * 8 + a];
        float4 o = make_float4(oacc[a][0] * inv, oacc[a][1] * inv,
                               oacc[a][2] * inv, oacc[a][3] * inv);
        *reinterpret_cast<float4*>(
            &g_ao[base_bh + (size_t)(q0 + ry * 8 + a) * DD + 4 * cx]) = o;
    }
}

// ---------------------------------------------------------------------------
// Launch
// ---------------------------------------------------------------------------
extern "C" void kernel_launch(void* const* d_in, const int* in_sizes, int n_in,
                              void* d_out, int out_size) {
    (void)in_sizes; (void)n_in; (void)out_size;
    const float* x  = (const float*)d_in[0];
    const float* wq = (const float*)d_in[1];
    const float* wk = (const float*)d_in[2];
    const float* wv = (const float*)d_in[3];
    const float* wo = (const float*)d_in[4];
    float* out = (float*)d_out;

    float *q, *k, *v, *ao;
    cudaGetSymbolAddress((void**)&q,  g_q);
    cudaGetSymbolAddress((void**)&k,  g_k);
    cudaGetSymbolAddress((void**)&v,  g_v);
    cudaGetSymbolAddress((void**)&ao, g_ao);

    // RoPE table (cheap; recomputed every call for determinism)
    rope_table_kernel<<<(SS * NPAIR + 255) / 256, 256>>>();

    // QKV projections: [4096,2048] = x @ W^T
    dim3 gemm_grid(DD / 128, BS / 128);
    sgemm_nt<<<gemm_grid, 256>>>(x, wq, q, BS, DD, DD);
    sgemm_nt<<<gemm_grid, 256>>>(x, wk, k, BS, DD, DD);
    sgemm_nt<<<gemm_grid, 256>>>(x, wv, v, BS, DD, DD);

    // RoPE on q, k
    rope_apply_kernel<<<(BS * (DD / 2) + 255) / 256, 256>>>();

    // Flash attention
    cudaFuncSetAttribute(flash_kernel,
                         cudaFuncAttributeMaxDynamicSharedMemorySize,
                         FLASH_SMEM_BYTES);
    dim3 fgrid(SS / 64, BB * HH);
    flash_kernel<<<fgrid, 256, FLASH_SMEM_BYTES>>>();

    // Output projection
    sgemm_nt<<<gemm_grid, 256>>>(ao, wo, out, BS, DD, DD);
}

// round 3
// speedup vs baseline: 1.7272x; 1.7272x over previous
#include <cuda_runtime.h>
#include <cuda_bf16.h>
#include <math.h>
#include <stdint.h>

// Problem constants
#define BB 2
#define SS 2048
#define DD 2048
#define HH 16
#define HD 128
#define BS (BB * SS)        // 4096 tokens
#define NPAIR (HD / 2)      // 64 rope pairs per head
#define KBIG (3 * DD)       // 6144: bf16x3 split-K
#define ITERS (KBIG / 64)   // 96 K-chunks of 64
#define STG 4               // cp.async pipeline stages

// ---------------------------------------------------------------------------
// Scratch (device globals -- no allocation allowed in kernel_launch)
// ---------------------------------------------------------------------------
__device__ float g_q[BS * DD];
__device__ float g_k[BS * DD];
__device__ float g_v[BS * DD];
__device__ float g_ao[BS * DD];
__device__ float g_cos[SS * NPAIR];
__device__ float g_sin[SS * NPAIR];
__device__ __nv_bfloat16 g_abig[(size_t)BS * KBIG];  // [hi | lo | hi]
__device__ __nv_bfloat16 g_wbig[(size_t)DD * KBIG];  // [hi | hi | lo]

// ---------------------------------------------------------------------------
// Helpers
// ---------------------------------------------------------------------------
__device__ __forceinline__ uint32_t smem_u32(const void* p) {
    uint32_t a;
    asm("{ .reg .u64 t; cvta.to.shared.u64 t, %1; cvt.u32.u64 %0, t; }"
        : "=r"(a) : "l"(p));
    return a;
}
#define CP_ASYNC16(smem, gptr) \
    asm volatile("cp.async.cg.shared.global [%0], [%1], 16;" \
                 :: "r"((uint32_t)(smem)), "l"((const void*)(gptr)) : "memory")
#define CP_COMMIT() asm volatile("cp.async.commit_group;" ::: "memory")

// ---------------------------------------------------------------------------
// RoPE table (double precision generation)
// ---------------------------------------------------------------------------
__global__ void rope_table_kernel() {
    int idx = blockIdx.x * blockDim.x + threadIdx.x;
    if (idx >= SS * NPAIR) return;
    int s = idx / NPAIR;
    int i = idx - s * NPAIR;
    double freq = (double)s * exp(((double)(-2 * i) / (double)HD) * log(10000.0));
    g_cos[idx] = (float)cos(freq);
    g_sin[idx] = (float)sin(freq);
}

// RoPE in place on g_q and g_k
__global__ void rope_apply_kernel() {
    int idx = blockIdx.x * blockDim.x + threadIdx.x;
    if (idx >= BS * (DD / 2)) return;
    int t = idx >> 10;
    int p = idx & 1023;
    int i = p & (NPAIR - 1);
    int s = t & (SS - 1);
    float c  = g_cos[(s << 6) + i];
    float sn = g_sin[(s << 6) + i];
    size_t base = ((size_t)t << 11) + ((size_t)p << 1);
    float2 q2 = *reinterpret_cast<float2*>(&g_q[base]);
    float2 k2 = *reinterpret_cast<float2*>(&g_k[base]);
    float2 qo = make_float2(q2.x * c - q2.y * sn, q2.x * sn + q2.y * c);
    float2 ko = make_float2(k2.x * c - k2.y * sn, k2.x * sn + k2.y * c);
    *reinterpret_cast<float2*>(&g_q[base]) = qo;
    *reinterpret_cast<float2*>(&g_k[base]) = ko;
}

// ---------------------------------------------------------------------------
// bf16x3 split: src fp32 [rows, 2048] -> dst bf16 [rows, 6144]
// mode 0 (activation): [hi | lo | hi];  mode 1 (weight): [hi | hi | lo]
// ---------------------------------------------------------------------------
__global__ void split3_kernel(const float* __restrict__ src,
                              __nv_bfloat16* __restrict__ dst,
                              int n, int mode) {
    int idx = blockIdx.x * blockDim.x + threadIdx.x;
    if (idx >= n) return;
    int r = idx >> 11;
    int c = idx & 2047;
    float v = src[idx];
    __nv_bfloat16 hi = __float2bfloat16(v);
    __nv_bfloat16 lo = __float2bfloat16(v - __bfloat162float(hi));
    size_t base = (size_t)r * KBIG + c;
    if (mode == 0) {
        dst[base] = hi; dst[base + DD] = lo; dst[base + 2 * DD] = hi;
    } else {
        dst[base] = hi; dst[base + DD] = hi; dst[base + 2 * DD] = lo;
    }
}

// ---------------------------------------------------------------------------
// HMMA GEMM: C[4096,2048] = A[4096,6144] * B[2048,6144]^T  (bf16 in, fp32 out)
// 128x128 CTA tile, BK=64, 4-stage cp.async pipeline, SW128-swizzled smem,
// mma.sync.m16n8k16 bf16 with fp32 register accumulators.
// ---------------------------------------------------------------------------
#define TILE_STAGE_BYTES 32768          // A(16KB) + B(16KB) per stage
#define GEMM_SMEM_BYTES (STG * TILE_STAGE_BYTES)  // 131072

__device__ __forceinline__ void issue_stage(
    uint32_t sb, int s, int tid,
    const __nv_bfloat16* __restrict__ Ag,
    const __nv_bfloat16* __restrict__ Bg)
{
    if (s < ITERS) {
        const int k0 = s * 64;
        const int slot = s & (STG - 1);
        uint32_t abase = sb + slot * TILE_STAGE_BYTES;
        uint32_t bbase = abase + 16384;
#pragma unroll
        for (int i = 0; i < 4; i++) {
            int id = tid + 256 * i;          // 0..1023 chunks of 16B
            int row = id >> 3;               // 0..127
            int c = id & 7;                  // 16B chunk within 128B row
            uint32_t off = (uint32_t)(row * 128 + ((c ^ (row & 7)) << 4));
            CP_ASYNC16(abase + off, Ag + (size_t)row * KBIG + k0 + c * 8);
            CP_ASYNC16(bbase + off, Bg + (size_t)row * KBIG + k0 + c * 8);
        }
    }
    CP_COMMIT();
}

__global__ __launch_bounds__(256, 1)
void gemm_hmma(const __nv_bfloat16* __restrict__ A,
               const __nv_bfloat16* __restrict__ Bw,
               float* __restrict__ C)
{
    extern __shared__ char smraw[];
    uint32_t sb = smem_u32(smraw);
    const int tid  = threadIdx.x;
    const int lane = tid & 31;
    const int warp = tid >> 5;
    const int wm = warp & 1;        // m half (64 rows)
    const int wn = warp >> 1;       // n quarter (32 cols)
    const int m0 = blockIdx.y * 128;
    const int n0 = blockIdx.x * 128;
    const __nv_bfloat16* Ag = A  + (size_t)m0 * KBIG;
    const __nv_bfloat16* Bg = Bw + (size_t)n0 * KBIG;

    float acc[4][4][4];
#pragma unroll
    for (int a = 0; a < 4; a++)
#pragma unroll
        for (int b = 0; b < 4; b++)
#pragma unroll
            for (int c = 0; c < 4; c++) acc[a][b][c] = 0.f;

    issue_stage(sb, 0, tid, Ag, Bg);
    issue_stage(sb, 1, tid, Ag, Bg);
    issue_stage(sb, 2, tid, Ag, Bg);

    for (int s = 0; s < ITERS; s++) {
        asm volatile("cp.async.wait_group 2;" ::: "memory");
        __syncthreads();
        const int slot = s & (STG - 1);
        uint32_t abase = sb + slot * TILE_STAGE_BYTES;
        uint32_t bbase = abase + 16384;

#pragma unroll
        for (int ks = 0; ks < 4; ks++) {
            uint32_t af[4][4];
            uint32_t bf[4][2];
#pragma unroll
            for (int mt = 0; mt < 4; mt++) {
                int row = wm * 64 + mt * 16 + (lane & 15);
                int ch  = ks * 2 + (lane >> 4);
                uint32_t ad = abase + (uint32_t)(row * 128 +
                                  ((ch ^ (row & 7)) << 4));
                asm volatile(
                    "ldmatrix.sync.aligned.m8n8.x4.shared.b16 {%0,%1,%2,%3}, [%4];"
                    : "=r"(af[mt][0]), "=r"(af[mt][1]),
                      "=r"(af[mt][2]), "=r"(af[mt][3])
                    : "r"(ad));
            }
#pragma unroll
            for (int np = 0; np < 2; np++) {
                int row = wn * 32 + np * 16 + ((lane >> 4) << 3) + (lane & 7);
                int ch  = ks * 2 + ((lane >> 3) & 1);
                uint32_t bd = bbase + (uint32_t)(row * 128 +
                                  ((ch ^ (row & 7)) << 4));
                asm volatile(
                    "ldmatrix.sync.aligned.m8n8.x4.shared.b16 {%0,%1,%2,%3}, [%4];"
                    : "=r"(bf[2 * np][0]), "=r"(bf[2 * np][1]),
                      "=r"(bf[2 * np + 1][0]), "=r"(bf[2 * np + 1][1])
                    : "r"(bd));
            }
#pragma unroll
            for (int mt = 0; mt < 4; mt++)
#pragma unroll
                for (int nt = 0; nt < 4; nt++)
                    asm volatile(
                        "mma.sync.aligned.m16n8k16.row.col.f32.bf16.bf16.f32 "
                        "{%0,%1,%2,%3}, {%4,%5,%6,%7}, {%8,%9}, {%0,%1,%2,%3};"
                        : "+f"(acc[mt][nt][0]), "+f"(acc[mt][nt][1]),
                          "+f"(acc[mt][nt][2]), "+f"(acc[mt][nt][3])
                        : "r"(af[mt][0]), "r"(af[mt][1]),
                          "r"(af[mt][2]), "r"(af[mt][3]),
                          "r"(bf[nt][0]), "r"(bf[nt][1]));
        }
        // Safe: slot(s+3) == slot(s-1); all warps finished compute(s-1)
        // before this iteration's __syncthreads.
        issue_stage(sb, s + 3, tid, Ag, Bg);
    }

    // Epilogue: fragment layout d0,d1 -> (row, col..col+1), d2,d3 -> row+8
#pragma unroll
    for (int mt = 0; mt < 4; mt++) {
#pragma unroll
        for (int nt = 0; nt < 4; nt++) {
            int row = m0 + wm * 64 + mt * 16 + (lane >> 2);
            int col = n0 + wn * 32 + nt * 8 + (lane & 3) * 2;
            float2 v0 = make_float2(acc[mt][nt][0], acc[mt][nt][1]);
            float2 v1 = make_float2(acc[mt][nt][2], acc[mt][nt][3]);
            *reinterpret_cast<float2*>(&C[(size_t)row * DD + col]) = v0;
            *reinterpret_cast<float2*>(&C[(size_t)(row + 8) * DD + col]) = v1;
        }
    }
}

// ---------------------------------------------------------------------------
// Flash attention (fp32, unchanged from R1): one block per (q-tile 64, b*h)
// ---------------------------------------------------------------------------
#define FLASH_SMEM_FLOATS (2 * 128 * 65 + 64 * 65 + 3 * 64)
#define FLASH_SMEM_BYTES  (FLASH_SMEM_FLOATS * 4)

__global__ __launch_bounds__(256, 2) void flash_kernel() {
    extern __shared__ float smf[];
    float* Qt  = smf;
    float* KV  = smf + 128 * 65;
    float* Pt  = smf + 2 * 128 * 65;
    float* m_s  = Pt + 64 * 65;
    float* l_s  = m_s + 64;
    float* al_s = l_s + 64;

    const int tid = threadIdx.x;
    const int q0  = blockIdx.x * 64;
    const int bh  = blockIdx.y;
    const int b   = bh >> 4;
    const int h   = bh & 15;
    const size_t base_bh = (size_t)b * SS * DD + (size_t)h * HD;

#pragma unroll
    for (int rep = 0; rep < 32; rep++) {
        int lin = rep * 256 + tid;
        int r = lin >> 7;
        int d = lin & 127;
        Qt[d * 65 + r] = g_q[base_bh + (size_t)(q0 + r) * DD + d];
    }

    if (tid < 64) { m_s[tid] = -INFINITY; l_s[tid] = 0.f; }

    float oacc[8][4];
#pragma unroll
    for (int a = 0; a < 8; a++)
#pragma unroll
        for (int c = 0; c < 4; c++) oacc[a][c] = 0.f;

    const int ty = tid >> 4, tx = tid & 15;
    const int ry = tid >> 5, cx = tid & 31;

    for (int kv0 = 0; kv0 < SS; kv0 += 64) {
        __syncthreads();

#pragma unroll
        for (int rep = 0; rep < 32; rep++) {
            int lin = rep * 256 + tid;
            int j = lin >> 7;
            int d = lin & 127;
            KV[d * 65 + j] = g_k[base_bh + (size_t)(kv0 + j) * DD + d];
        }
        __syncthreads();

        float sacc[4][4];
#pragma unroll
        for (int a = 0; a < 4; a++)
#pragma unroll
            for (int c = 0; c < 4; c++) sacc[a][c] = 0.f;

#pragma unroll 4
        for (int d = 0; d < 128; d++) {
            float ar[4], br[4];
#pragma unroll
            for (int a = 0; a < 4; a++) ar[a] = Qt[d * 65 + 4 * ty + a];
#pragma unroll
            for (int c = 0; c < 4; c++) br[c] = KV[d * 65 + 4 * tx + c];
#pragma unroll
            for (int a = 0; a < 4; a++)
#pragma unroll
                for (int c = 0; c < 4; c++)
                    sacc[a][c] += ar[a] * br[c];
        }
#pragma unroll
        for (int c = 0; c < 4; c++)
#pragma unroll
            for (int a = 0; a < 4; a++)
                Pt[(4 * tx + c) * 65 + 4 * ty + a] =
                    sacc[a][c] * 0.08838834764831845f;
        __syncthreads();

#pragma unroll
        for (int rep = 0; rep < 8; rep++) {
            int lin4 = rep * 256 + tid;
            int j  = lin4 >> 5;
            int d4 = (lin4 & 31) << 2;
            *reinterpret_cast<float4*>(&KV[j * 128 + d4]) =
                *reinterpret_cast<const float4*>(
                    &g_v[base_bh + (size_t)(kv0 + j) * DD + d4]);
        }

        if (tid < 64) {
            const int r = tid;
            float mi = m_s[r];
            float mx = mi;
#pragma unroll 8
            for (int c = 0; c < 64; c++)
                mx = fmaxf(mx, Pt[c * 65 + r]);
            float alpha = __expf(mi - mx);
            float sum = 0.f;
#pragma unroll 8
            for (int c = 0; c < 64; c++) {
                float p = __expf(Pt[c * 65 + r] - mx);
                Pt[c * 65 + r] = p;
                sum += p;
            }
            m_s[r]  = mx;
            l_s[r]  = l_s[r] * alpha + sum;
            al_s[r] = alpha;
        }
        __syncthreads();

        float al[8];
#pragma unroll
        for (int a = 0; a < 8; a++) al[a] = al_s[ry * 8 + a];
#pragma unroll
        for (int a = 0; a < 8; a++)
#pragma unroll
            for (int c = 0; c < 4; c++) oacc[a][c] *= al[a];

#pragma unroll 2
        for (int j = 0; j < 64; j++) {
            float4 vv = *reinterpret_cast<float4*>(&KV[j * 128 + 4 * cx]);
#pragma unroll
            for (int a = 0; a < 8; a++) {
                float p = Pt[j * 65 + ry * 8 + a];
                oacc[a][0] += p * vv.x;
                oacc[a][1] += p * vv.y;
                oacc[a][2] += p * vv.z;
                oacc[a][3] += p * vv.w;
            }
        }
    }

#pragma unroll
    for (int a = 0; a < 8; a++) {
        float inv = 1.0f / l_s[ry * 8 + a];
        float4 o = make_float4(oacc[a][0] * inv, oacc[a][1] * inv,
                               oacc[a][2] * inv, oacc[a][3] * inv);
        *reinterpret_cast<float4*>(
            &g_ao[base_bh + (size_t)(q0 + ry * 8 + a) * DD + 4 * cx]) = o;
    }
}

// ---------------------------------------------------------------------------
// Launch
// ---------------------------------------------------------------------------
extern "C" void kernel_launch(void* const* d_in, const int* in_sizes, int n_in,
                              void* d_out, int out_size) {
    (void)in_sizes; (void)n_in; (void)out_size;
    const float* x  = (const float*)d_in[0];
    const float* wq = (const float*)d_in[1];
    const float* wk = (const float*)d_in[2];
    const float* wv = (const float*)d_in[3];
    const float* wo = (const float*)d_in[4];
    float* out = (float*)d_out;

    float *q, *k, *v, *ao;
    __nv_bfloat16 *abig, *wbig;
    cudaGetSymbolAddress((void**)&q,    g_q);
    cudaGetSymbolAddress((void**)&k,    g_k);
    cudaGetSymbolAddress((void**)&v,    g_v);
    cudaGetSymbolAddress((void**)&ao,   g_ao);
    cudaGetSymbolAddress((void**)&abig, g_abig);
    cudaGetSymbolAddress((void**)&wbig, g_wbig);

    cudaFuncSetAttribute(gemm_hmma,
                         cudaFuncAttributeMaxDynamicSharedMemorySize,
                         GEMM_SMEM_BYTES);
    cudaFuncSetAttribute(flash_kernel,
                         cudaFuncAttributeMaxDynamicSharedMemorySize,
                         FLASH_SMEM_BYTES);

    const int n_act = BS * DD;
    const int n_w   = DD * DD;
    dim3 ggrid(DD / 128, BS / 128);  // (16, 32)

    rope_table_kernel<<<(SS * NPAIR + 255) / 256, 256>>>();

    split3_kernel<<<(n_act + 255) / 256, 256>>>(x, abig, n_act, 0);

    split3_kernel<<<(n_w + 255) / 256, 256>>>(wq, wbig, n_w, 1);
    gemm_hmma<<<ggrid, 256, GEMM_SMEM_BYTES>>>(abig, wbig, q);
    split3_kernel<<<(n_w + 255) / 256, 256>>>(wk, wbig, n_w, 1);
    gemm_hmma<<<ggrid, 256, GEMM_SMEM_BYTES>>>(abig, wbig, k);
    split3_kernel<<<(n_w + 255) / 256, 256>>>(wv, wbig, n_w, 1);
    gemm_hmma<<<ggrid, 256, GEMM_SMEM_BYTES>>>(abig, wbig, v);

    rope_apply_kernel<<<(BS * (DD / 2) + 255) / 256, 256>>>();

    dim3 fgrid(SS / 64, BB * HH);
    flash_kernel<<<fgrid, 256, FLASH_SMEM_BYTES>>>();

    split3_kernel<<<(n_act + 255) / 256, 256>>>(ao, abig, n_act, 0);
    split3_kernel<<<(n_w + 255) / 256, 256>>>(wo, wbig, n_w, 1);
    gemm_hmma<<<ggrid, 256, GEMM_SMEM_BYTES>>>(abig, wbig, out);
}

// round 4
// speedup vs baseline: 1.7877x; 1.0350x over previous
#include <cuda_runtime.h>
#include <cuda_bf16.h>
#include <math.h>
#include <stdint.h>

// Problem constants
#define BB 2
#define SS 2048
#define DD 2048
#define HH 16
#define HD 128
#define BS (BB * SS)        // 4096 tokens
#define NPAIR (HD / 2)      // 64 rope pairs per head
#define KBIG (3 * DD)       // 6144: bf16x3 split-K
#define ITERS (KBIG / 64)   // 96 K-chunks of 64
#define STG 4               // cp.async pipeline stages

// ---------------------------------------------------------------------------
// Scratch (device globals -- no allocation allowed in kernel_launch)
// ---------------------------------------------------------------------------
__device__ float g_q[BS * DD];
__device__ float g_k[BS * DD];
__device__ float g_v[BS * DD];
__device__ float g_ao[BS * DD];
__device__ float g_cos[SS * NPAIR];
__device__ float g_sin[SS * NPAIR];
__device__ __nv_bfloat16 g_abig[(size_t)BS * KBIG];  // [hi | lo | hi]
__device__ __nv_bfloat16 g_wbig[(size_t)DD * KBIG];  // [hi | hi | lo]

// ---------------------------------------------------------------------------
// Helpers
// ---------------------------------------------------------------------------
__device__ __forceinline__ uint32_t smem_u32(const void* p) {
    uint32_t a;
    asm("{ .reg .u64 t; cvta.to.shared.u64 t, %1; cvt.u32.u64 %0, t; }"
        : "=r"(a) : "l"(p));
    return a;
}
#define CP_ASYNC16(smem, gptr) \
    asm volatile("cp.async.cg.shared.global [%0], [%1], 16;" \
                 :: "r"((uint32_t)(smem)), "l"((const void*)(gptr)) : "memory")
#define CP_COMMIT() asm volatile("cp.async.commit_group;" ::: "memory")

// ---------------------------------------------------------------------------
// RoPE table (double precision generation)
// ---------------------------------------------------------------------------
__global__ void rope_table_kernel() {
    int idx = blockIdx.x * blockDim.x + threadIdx.x;
    if (idx >= SS * NPAIR) return;
    int s = idx / NPAIR;
    int i = idx - s * NPAIR;
    double freq = (double)s * exp(((double)(-2 * i) / (double)HD) * log(10000.0));
    g_cos[idx] = (float)cos(freq);
    g_sin[idx] = (float)sin(freq);
}

// RoPE in place on g_q and g_k
__global__ void rope_apply_kernel() {
    int idx = blockIdx.x * blockDim.x + threadIdx.x;
    if (idx >= BS * (DD / 2)) return;
    int t = idx >> 10;
    int p = idx & 1023;
    int i = p & (NPAIR - 1);
    int s = t & (SS - 1);
    float c  = g_cos[(s << 6) + i];
    float sn = g_sin[(s << 6) + i];
    size_t base = ((size_t)t << 11) + ((size_t)p << 1);
    float2 q2 = *reinterpret_cast<float2*>(&g_q[base]);
    float2 k2 = *reinterpret_cast<float2*>(&g_k[base]);
    float2 qo = make_float2(q2.x * c - q2.y * sn, q2.x * sn + q2.y * c);
    float2 ko = make_float2(k2.x * c - k2.y * sn, k2.x * sn + k2.y * c);
    *reinterpret_cast<float2*>(&g_q[base]) = qo;
    *reinterpret_cast<float2*>(&g_k[base]) = ko;
}

// ---------------------------------------------------------------------------
// bf16x3 split: src fp32 [rows, 2048] -> dst bf16 [rows, 6144]
// mode 0 (activation): [hi | lo | hi];  mode 1 (weight): [hi | hi | lo]
// ---------------------------------------------------------------------------
__global__ void split3_kernel(const float* __restrict__ src,
                              __nv_bfloat16* __restrict__ dst,
                              int n, int mode) {
    int idx = blockIdx.x * blockDim.x + threadIdx.x;
    if (idx >= n) return;
    int r = idx >> 11;
    int c = idx & 2047;
    float v = src[idx];
    __nv_bfloat16 hi = __float2bfloat16(v);
    __nv_bfloat16 lo = __float2bfloat16(v - __bfloat162float(hi));
    size_t base = (size_t)r * KBIG + c;
    if (mode == 0) {
        dst[base] = hi; dst[base + DD] = lo; dst[base + 2 * DD] = hi;
    } else {
        dst[base] = hi; dst[base + DD] = hi; dst[base + 2 * DD] = lo;
    }
}

// ---------------------------------------------------------------------------
// HMMA GEMM: C[4096,2048] = A[4096,6144] * B[2048,6144]^T  (bf16 in, fp32 out)
// 128x128 CTA tile, BK=64, 4-stage cp.async pipeline, SW128-swizzled smem,
// mma.sync.m16n8k16 bf16 with fp32 register accumulators.
// ---------------------------------------------------------------------------
#define TILE_STAGE_BYTES 32768          // A(16KB) + B(16KB) per stage
#define GEMM_SMEM_BYTES (STG * TILE_STAGE_BYTES)  // 131072

__device__ __forceinline__ void issue_stage(
    uint32_t sb, int s, int tid,
    const __nv_bfloat16* __restrict__ Ag,
    const __nv_bfloat16* __restrict__ Bg)
{
    if (s < ITERS) {
        const int k0 = s * 64;
        const int slot = s & (STG - 1);
        uint32_t abase = sb + slot * TILE_STAGE_BYTES;
        uint32_t bbase = abase + 16384;
#pragma unroll
        for (int i = 0; i < 4; i++) {
            int id = tid + 256 * i;          // 0..1023 chunks of 16B
            int row = id >> 3;               // 0..127
            int c = id & 7;                  // 16B chunk within 128B row
            uint32_t off = (uint32_t)(row * 128 + ((c ^ (row & 7)) << 4));
            CP_ASYNC16(abase + off, Ag + (size_t)row * KBIG + k0 + c * 8);
            CP_ASYNC16(bbase + off, Bg + (size_t)row * KBIG + k0 + c * 8);
        }
    }
    CP_COMMIT();
}

__global__ __launch_bounds__(256, 1)
void gemm_hmma(const __nv_bfloat16* __restrict__ A,
               const __nv_bfloat16* __restrict__ Bw,
               float* __restrict__ C)
{
    extern __shared__ char smraw[];
    uint32_t sb = smem_u32(smraw);
    const int tid  = threadIdx.x;
    const int lane = tid & 31;
    const int warp = tid >> 5;
    const int wm = warp & 1;        // m half (64 rows)
    const int wn = warp >> 1;       // n quarter (32 cols)
    const int m0 = blockIdx.y * 128;
    const int n0 = blockIdx.x * 128;
    const __nv_bfloat16* Ag = A  + (size_t)m0 * KBIG;
    const __nv_bfloat16* Bg = Bw + (size_t)n0 * KBIG;

    float acc[4][4][4];
#pragma unroll
    for (int a = 0; a < 4; a++)
#pragma unroll
        for (int b = 0; b < 4; b++)
#pragma unroll
            for (int c = 0; c < 4; c++) acc[a][b][c] = 0.f;

    issue_stage(sb, 0, tid, Ag, Bg);
    issue_stage(sb, 1, tid, Ag, Bg);
    issue_stage(sb, 2, tid, Ag, Bg);

    for (int s = 0; s < ITERS; s++) {
        asm volatile("cp.async.wait_group 2;" ::: "memory");
        __syncthreads();
        const int slot = s & (STG - 1);
        uint32_t abase = sb + slot * TILE_STAGE_BYTES;
        uint32_t bbase = abase + 16384;

#pragma unroll
        for (int ks = 0; ks < 4; ks++) {
            uint32_t af[4][4];
            uint32_t bf[4][2];
#pragma unroll
            for (int mt = 0; mt < 4; mt++) {
                int row = wm * 64 + mt * 16 + (lane & 15);
                int ch  = ks * 2 + (lane >> 4);
                uint32_t ad = abase + (uint32_t)(row * 128 +
                                  ((ch ^ (row & 7)) << 4));
                asm volatile(
                    "ldmatrix.sync.aligned.m8n8.x4.shared.b16 {%0,%1,%2,%3}, [%4];"
                    : "=r"(af[mt][0]), "=r"(af[mt][1]),
                      "=r"(af[mt][2]), "=r"(af[mt][3])
                    : "r"(ad));
            }
#pragma unroll
            for (int np = 0; np < 2; np++) {
                int row = wn * 32 + np * 16 + ((lane >> 4) << 3) + (lane & 7);
                int ch  = ks * 2 + ((lane >> 3) & 1);
                uint32_t bd = bbase + (uint32_t)(row * 128 +
                                  ((ch ^ (row & 7)) << 4));
                asm volatile(
                    "ldmatrix.sync.aligned.m8n8.x4.shared.b16 {%0,%1,%2,%3}, [%4];"
                    : "=r"(bf[2 * np][0]), "=r"(bf[2 * np][1]),
                      "=r"(bf[2 * np + 1][0]), "=r"(bf[2 * np + 1][1])
                    : "r"(bd));
            }
#pragma unroll
            for (int mt = 0; mt < 4; mt++)
#pragma unroll
                for (int nt = 0; nt < 4; nt++)
                    asm volatile(
                        "mma.sync.aligned.m16n8k16.row.col.f32.bf16.bf16.f32 "
                        "{%0,%1,%2,%3}, {%4,%5,%6,%7}, {%8,%9}, {%0,%1,%2,%3};"
                        : "+f"(acc[mt][nt][0]), "+f"(acc[mt][nt][1]),
                          "+f"(acc[mt][nt][2]), "+f"(acc[mt][nt][3])
                        : "r"(af[mt][0]), "r"(af[mt][1]),
                          "r"(af[mt][2]), "r"(af[mt][3]),
                          "r"(bf[nt][0]), "r"(bf[nt][1]));
        }
        // Safe: slot(s+3) == slot(s-1); all warps finished compute(s-1)
        // before this iteration's __syncthreads.
        issue_stage(sb, s + 3, tid, Ag, Bg);
    }

    // Epilogue: fragment layout d0,d1 -> (row, col..col+1), d2,d3 -> row+8
#pragma unroll
    for (int mt = 0; mt < 4; mt++) {
#pragma unroll
        for (int nt = 0; nt < 4; nt++) {
            int row = m0 + wm * 64 + mt * 16 + (lane >> 2);
            int col = n0 + wn * 32 + nt * 8 + (lane & 3) * 2;
            float2 v0 = make_float2(acc[mt][nt][0], acc[mt][nt][1]);
            float2 v1 = make_float2(acc[mt][nt][2], acc[mt][nt][3]);
            *reinterpret_cast<float2*>(&C[(size_t)row * DD + col]) = v0;
            *reinterpret_cast<float2*>(&C[(size_t)(row + 8) * DD + col]) = v1;
        }
    }
}

// ---------------------------------------------------------------------------
// Flash attention (fp32, unchanged from R1): one block per (q-tile 64, b*h)
// ---------------------------------------------------------------------------
#define FLASH_SMEM_FLOATS (2 * 128 * 65 + 64 * 65 + 3 * 64)
#define FLASH_SMEM_BYTES  (FLASH_SMEM_FLOATS * 4)

__global__ __launch_bounds__(256, 2) void flash_kernel() {
    extern __shared__ float smf[];
    float* Qt  = smf;
    float* KV  = smf + 128 * 65;
    float* Pt  = smf + 2 * 128 * 65;
    float* m_s  = Pt + 64 * 65;
    float* l_s  = m_s + 64;
    float* al_s = l_s + 64;

    const int tid = threadIdx.x;
    const int q0  = blockIdx.x * 64;
    const int bh  = blockIdx.y;
    const int b   = bh >> 4;
    const int h   = bh & 15;
    const size_t base_bh = (size_t)b * SS * DD + (size_t)h * HD;

#pragma unroll
    for (int rep = 0; rep < 32; rep++) {
        int lin = rep * 256 + tid;
        int r = lin >> 7;
        int d = lin & 127;
        Qt[d * 65 + r] = g_q[base_bh + (size_t)(q0 + r) * DD + d];
    }

    if (tid < 64) { m_s[tid] = -INFINITY; l_s[tid] = 0.f; }

    float oacc[8][4];
#pragma unroll
    for (int a = 0; a < 8; a++)
#pragma unroll
        for (int c = 0; c < 4; c++) oacc[a][c] = 0.f;

    const int ty = tid >> 4, tx = tid & 15;
    const int ry = tid >> 5, cx = tid & 31;

    for (int kv0 = 0; kv0 < SS; kv0 += 64) {
        __syncthreads();

#pragma unroll
        for (int rep = 0; rep < 32; rep++) {
            int lin = rep * 256 + tid;
            int j = lin >> 7;
            int d = lin & 127;
            KV[d * 65 + j] = g_k[base_bh + (size_t)(kv0 + j) * DD + d];
        }
        __syncthreads();

        float sacc[4][4];
#pragma unroll
        for (int a = 0; a < 4; a++)
#pragma unroll
            for (int c = 0; c < 4; c++) sacc[a][c] = 0.f;

#pragma unroll 4
        for (int d = 0; d < 128; d++) {
            float ar[4], br[4];
#pragma unroll
            for (int a = 0; a < 4; a++) ar[a] = Qt[d * 65 + 4 * ty + a];
#pragma unroll
            for (int c = 0; c < 4; c++) br[c] = KV[d * 65 + 4 * tx + c];
#pragma unroll
            for (int a = 0; a < 4; a++)
#pragma unroll
                for (int c = 0; c < 4; c++)
                    sacc[a][c] += ar[a] * br[c];
        }
#pragma unroll
        for (int c = 0; c < 4; c++)
#pragma unroll
            for (int a = 0; a < 4; a++)
                Pt[(4 * tx + c) * 65 + 4 * ty + a] =
                    sacc[a][c] * 0.08838834764831845f;
        __syncthreads();

#pragma unroll
        for (int rep = 0; rep < 8; rep++) {
            int lin4 = rep * 256 + tid;
            int j  = lin4 >> 5;
            int d4 = (lin4 & 31) << 2;
            *reinterpret_cast<float4*>(&KV[j * 128 + d4]) =
                *reinterpret_cast<const float4*>(
                    &g_v[base_bh + (size_t)(kv0 + j) * DD + d4]);
        }

        if (tid < 64) {
            const int r = tid;
            float mi = m_s[r];
            float mx = mi;
#pragma unroll 8
            for (int c = 0; c < 64; c++)
                mx = fmaxf(mx, Pt[c * 65 + r]);
            float alpha = __expf(mi - mx);
            float sum = 0.f;
#pragma unroll 8
            for (int c = 0; c < 64; c++) {
                float p = __expf(Pt[c * 65 + r] - mx);
                Pt[c * 65 + r] = p;
                sum += p;
            }
            m_s[r]  = mx;
            l_s[r]  = l_s[r] * alpha + sum;
            al_s[r] = alpha;
        }
        __syncthreads();

        float al[8];
#pragma unroll
        for (int a = 0; a < 8; a++) al[a] = al_s[ry * 8 + a];
#pragma unroll
        for (int a = 0; a < 8; a++)
#pragma unroll
            for (int c = 0; c < 4; c++) oacc[a][c] *= al[a];

#pragma unroll 2
        for (int j = 0; j < 64; j++) {
            float4 vv = *reinterpret_cast<float4*>(&KV[j * 128 + 4 * cx]);
#pragma unroll
            for (int a = 0; a < 8; a++) {
                float p = Pt[j * 65 + ry * 8 + a];
                oacc[a][0] += p * vv.x;
                oacc[a][1] += p * vv.y;
                oacc[a][2] += p * vv.z;
                oacc[a][3] += p * vv.w;
            }
        }
    }

#pragma unroll
    for (int a = 0; a < 8; a++) {
        float inv = 1.0f / l_s[ry * 8 + a];
        float4 o = make_float4(oacc[a][0] * inv, oacc[a][1] * inv,
                               oacc[a][2] * inv, oacc[a][3] * inv);
        *reinterpret_cast<float4*>(
            &g_ao[base_bh + (size_t)(q0 + ry * 8 + a) * DD + 4 * cx]) = o;
    }
}

// ---------------------------------------------------------------------------
// Launch
// ---------------------------------------------------------------------------
extern "C" void kernel_launch(void* const* d_in, const int* in_sizes, int n_in,
                              void* d_out, int out_size) {
    (void)in_sizes; (void)n_in; (void)out_size;
    const float* x  = (const float*)d_in[0];
    const float* wq = (const float*)d_in[1];
    const float* wk = (const float*)d_in[2];
    const float* wv = (const float*)d_in[3];
    const float* wo = (const float*)d_in[4];
    float* out = (float*)d_out;

    float *q, *k, *v, *ao;
    __nv_bfloat16 *abig, *wbig;
    cudaGetSymbolAddress((void**)&q,    g_q);
    cudaGetSymbolAddress((void**)&k,    g_k);
    cudaGetSymbolAddress((void**)&v,    g_v);
    cudaGetSymbolAddress((void**)&ao,   g_ao);
    cudaGetSymbolAddress((void**)&abig, g_abig);
    cudaGetSymbolAddress((void**)&wbig, g_wbig);

    cudaFuncSetAttribute(gemm_hmma,
                         cudaFuncAttributeMaxDynamicSharedMemorySize,
                         GEMM_SMEM_BYTES);
    cudaFuncSetAttribute(flash_kernel,
                         cudaFuncAttributeMaxDynamicSharedMemorySize,
                         FLASH_SMEM_BYTES);

    const int n_act = BS * DD;
    const int n_w   = DD * DD;
    dim3 ggrid(DD / 128, BS / 128);  // (16, 32)

    rope_table_kernel<<<(SS * NPAIR + 255) / 256, 256>>>();

    split3_kernel<<<(n_act + 255) / 256, 256>>>(x, abig, n_act, 0);

    split3_kernel<<<(n_w + 255) / 256, 256>>>(wq, wbig, n_w, 1);
    gemm_hmma<<<ggrid, 256, GEMM_SMEM_BYTES>>>(abig, wbig, q);
    split3_kernel<<<(n_w + 255) / 256, 256>>>(wk, wbig, n_w, 1);
    gemm_hmma<<<ggrid, 256, GEMM_SMEM_BYTES>>>(abig, wbig, k);
    split3_kernel<<<(n_w + 255) / 256, 256>>>(wv, wbig, n_w, 1);
    gemm_hmma<<<ggrid, 256, GEMM_SMEM_BYTES>>>(abig, wbig, v);

    rope_apply_kernel<<<(BS * (DD / 2) + 255) / 256, 256>>>();

    dim3 fgrid(SS / 64, BB * HH);
    flash_kernel<<<fgrid, 256, FLASH_SMEM_BYTES>>>();

    split3_kernel<<<(n_act + 255) / 256, 256>>>(ao, abig, n_act, 0);
    split3_kernel<<<(n_w + 255) / 256, 256>>>(wo, wbig, n_w, 1);
    gemm_hmma<<<ggrid, 256, GEMM_SMEM_BYTES>>>(abig, wbig, out);
}

// round 5
// speedup vs baseline: 1.7889x; 1.0007x over previous
#include <cuda_runtime.h>
#include <cuda_bf16.h>
#include <math.h>
#include <stdint.h>

// Problem constants
#define BB 2
#define SS 2048
#define DD 2048
#define HH 16
#define HD 128
#define BS (BB * SS)        // 4096 tokens
#define NPAIR (HD / 2)      // 64 rope pairs per head
#define KBIG (3 * DD)       // 6144: bf16x3 split-K
#define ITERS (KBIG / 64)   // 96 K-chunks of 64
#define STG 4               // cp.async pipeline stages

// ---------------------------------------------------------------------------
// Scratch (device globals -- no allocation allowed in kernel_launch)
// ---------------------------------------------------------------------------
__device__ float g_q[BS * DD];
__device__ float g_k[BS * DD];
__device__ float g_v[BS * DD];
__device__ float g_ao[BS * DD];
__device__ float g_cos[SS * NPAIR];
__device__ float g_sin[SS * NPAIR];
__device__ __nv_bfloat16 g_abig[(size_t)BS * KBIG];  // [hi | lo | hi]
__device__ __nv_bfloat16 g_wbig[(size_t)DD * KBIG];  // [hi | hi | lo]

// ---------------------------------------------------------------------------
// Helpers
// ---------------------------------------------------------------------------
__device__ __forceinline__ uint32_t smem_u32(const void* p) {
    uint32_t a;
    asm("{ .reg .u64 t; cvta.to.shared.u64 t, %1; cvt.u32.u64 %0, t; }"
        : "=r"(a) : "l"(p));
    return a;
}
#define CP_ASYNC16(smem, gptr) \
    asm volatile("cp.async.cg.shared.global [%0], [%1], 16;" \
                 :: "r"((uint32_t)(smem)), "l"((const void*)(gptr)) : "memory")
#define CP_COMMIT() asm volatile("cp.async.commit_group;" ::: "memory")

// ---------------------------------------------------------------------------
// RoPE table (double precision generation)
// ---------------------------------------------------------------------------
__global__ void rope_table_kernel() {
    int idx = blockIdx.x * blockDim.x + threadIdx.x;
    if (idx >= SS * NPAIR) return;
    int s = idx / NPAIR;
    int i = idx - s * NPAIR;
    double freq = (double)s * exp(((double)(-2 * i) / (double)HD) * log(10000.0));
    g_cos[idx] = (float)cos(freq);
    g_sin[idx] = (float)sin(freq);
}

// RoPE in place on g_q and g_k
__global__ void rope_apply_kernel() {
    int idx = blockIdx.x * blockDim.x + threadIdx.x;
    if (idx >= BS * (DD / 2)) return;
    int t = idx >> 10;
    int p = idx & 1023;
    int i = p & (NPAIR - 1);
    int s = t & (SS - 1);
    float c  = g_cos[(s << 6) + i];
    float sn = g_sin[(s << 6) + i];
    size_t base = ((size_t)t << 11) + ((size_t)p << 1);
    float2 q2 = *reinterpret_cast<float2*>(&g_q[base]);
    float2 k2 = *reinterpret_cast<float2*>(&g_k[base]);
    float2 qo = make_float2(q2.x * c - q2.y * sn, q2.x * sn + q2.y * c);
    float2 ko = make_float2(k2.x * c - k2.y * sn, k2.x * sn + k2.y * c);
    *reinterpret_cast<float2*>(&g_q[base]) = qo;
    *reinterpret_cast<float2*>(&g_k[base]) = ko;
}

// ---------------------------------------------------------------------------
// bf16x3 split: src fp32 [rows, 2048] -> dst bf16 [rows, 6144]
// mode 0 (activation): [hi | lo | hi];  mode 1 (weight): [hi | hi | lo]
// ---------------------------------------------------------------------------
__global__ void split3_kernel(const float* __restrict__ src,
                              __nv_bfloat16* __restrict__ dst,
                              int n, int mode) {
    int idx = blockIdx.x * blockDim.x + threadIdx.x;
    if (idx >= n) return;
    int r = idx >> 11;
    int c = idx & 2047;
    float v = src[idx];
    __nv_bfloat16 hi = __float2bfloat16(v);
    __nv_bfloat16 lo = __float2bfloat16(v - __bfloat162float(hi));
    size_t base = (size_t)r * KBIG + c;
    if (mode == 0) {
        dst[base] = hi; dst[base + DD] = lo; dst[base + 2 * DD] = hi;
    } else {
        dst[base] = hi; dst[base + DD] = hi; dst[base + 2 * DD] = lo;
    }
}

// ---------------------------------------------------------------------------
// HMMA GEMM: C[4096,2048] = A[4096,6144] * B[2048,6144]^T  (bf16 in, fp32 out)
// 128x128 CTA tile, BK=64, 4-stage cp.async pipeline, SW128-swizzled smem,
// mma.sync.m16n8k16 bf16 with fp32 register accumulators.
// ---------------------------------------------------------------------------
#define TILE_STAGE_BYTES 32768          // A(16KB) + B(16KB) per stage
#define GEMM_SMEM_BYTES (STG * TILE_STAGE_BYTES)  // 131072

__device__ __forceinline__ void issue_stage(
    uint32_t sb, int s, int tid,
    const __nv_bfloat16* __restrict__ Ag,
    const __nv_bfloat16* __restrict__ Bg)
{
    if (s < ITERS) {
        const int k0 = s * 64;
        const int slot = s & (STG - 1);
        uint32_t abase = sb + slot * TILE_STAGE_BYTES;
        uint32_t bbase = abase + 16384;
#pragma unroll
        for (int i = 0; i < 4; i++) {
            int id = tid + 256 * i;          // 0..1023 chunks of 16B
            int row = id >> 3;               // 0..127
            int c = id & 7;                  // 16B chunk within 128B row
            uint32_t off = (uint32_t)(row * 128 + ((c ^ (row & 7)) << 4));
            CP_ASYNC16(abase + off, Ag + (size_t)row * KBIG + k0 + c * 8);
            CP_ASYNC16(bbase + off, Bg + (size_t)row * KBIG + k0 + c * 8);
        }
    }
    CP_COMMIT();
}

__global__ __launch_bounds__(256, 1)
void gemm_hmma(const __nv_bfloat16* __restrict__ A,
               const __nv_bfloat16* __restrict__ Bw,
               float* __restrict__ C)
{
    extern __shared__ char smraw[];
    uint32_t sb = smem_u32(smraw);
    const int tid  = threadIdx.x;
    const int lane = tid & 31;
    const int warp = tid >> 5;
    const int wm = warp & 1;        // m half (64 rows)
    const int wn = warp >> 1;       // n quarter (32 cols)
    const int m0 = blockIdx.y * 128;
    const int n0 = blockIdx.x * 128;
    const __nv_bfloat16* Ag = A  + (size_t)m0 * KBIG;
    const __nv_bfloat16* Bg = Bw + (size_t)n0 * KBIG;

    float acc[4][4][4];
#pragma unroll
    for (int a = 0; a < 4; a++)
#pragma unroll
        for (int b = 0; b < 4; b++)
#pragma unroll
            for (int c = 0; c < 4; c++) acc[a][b][c] = 0.f;

    issue_stage(sb, 0, tid, Ag, Bg);
    issue_stage(sb, 1, tid, Ag, Bg);
    issue_stage(sb, 2, tid, Ag, Bg);

    for (int s = 0; s < ITERS; s++) {
        asm volatile("cp.async.wait_group 2;" ::: "memory");
        __syncthreads();
        const int slot = s & (STG - 1);
        uint32_t abase = sb + slot * TILE_STAGE_BYTES;
        uint32_t bbase = abase + 16384;

#pragma unroll
        for (int ks = 0; ks < 4; ks++) {
            uint32_t af[4][4];
            uint32_t bf[4][2];
#pragma unroll
            for (int mt = 0; mt < 4; mt++) {
                int row = wm * 64 + mt * 16 + (lane & 15);
                int ch  = ks * 2 + (lane >> 4);
                uint32_t ad = abase + (uint32_t)(row * 128 +
                                  ((ch ^ (row & 7)) << 4));
                asm volatile(
                    "ldmatrix.sync.aligned.m8n8.x4.shared.b16 {%0,%1,%2,%3}, [%4];"
                    : "=r"(af[mt][0]), "=r"(af[mt][1]),
                      "=r"(af[mt][2]), "=r"(af[mt][3])
                    : "r"(ad));
            }
#pragma unroll
            for (int np = 0; np < 2; np++) {
                int row = wn * 32 + np * 16 + ((lane >> 4) << 3) + (lane & 7);
                int ch  = ks * 2 + ((lane >> 3) & 1);
                uint32_t bd = bbase + (uint32_t)(row * 128 +
                                  ((ch ^ (row & 7)) << 4));
                asm volatile(
                    "ldmatrix.sync.aligned.m8n8.x4.shared.b16 {%0,%1,%2,%3}, [%4];"
                    : "=r"(bf[2 * np][0]), "=r"(bf[2 * np][1]),
                      "=r"(bf[2 * np + 1][0]), "=r"(bf[2 * np + 1][1])
                    : "r"(bd));
            }
#pragma unroll
            for (int mt = 0; mt < 4; mt++)
#pragma unroll
                for (int nt = 0; nt < 4; nt++)
                    asm volatile(
                        "mma.sync.aligned.m16n8k16.row.col.f32.bf16.bf16.f32 "
                        "{%0,%1,%2,%3}, {%4,%5,%6,%7}, {%8,%9}, {%0,%1,%2,%3};"
                        : "+f"(acc[mt][nt][0]), "+f"(acc[mt][nt][1]),
                          "+f"(acc[mt][nt][2]), "+f"(acc[mt][nt][3])
                        : "r"(af[mt][0]), "r"(af[mt][1]),
                          "r"(af[mt][2]), "r"(af[mt][3]),
                          "r"(bf[nt][0]), "r"(bf[nt][1]));
        }
        // Safe: slot(s+3) == slot(s-1); all warps finished compute(s-1)
        // before this iteration's __syncthreads.
        issue_stage(sb, s + 3, tid, Ag, Bg);
    }

    // Epilogue: fragment layout d0,d1 -> (row, col..col+1), d2,d3 -> row+8
#pragma unroll
    for (int mt = 0; mt < 4; mt++) {
#pragma unroll
        for (int nt = 0; nt < 4; nt++) {
            int row = m0 + wm * 64 + mt * 16 + (lane >> 2);
            int col = n0 + wn * 32 + nt * 8 + (lane & 3) * 2;
            float2 v0 = make_float2(acc[mt][nt][0], acc[mt][nt][1]);
            float2 v1 = make_float2(acc[mt][nt][2], acc[mt][nt][3]);
            *reinterpret_cast<float2*>(&C[(size_t)row * DD + col]) = v0;
            *reinterpret_cast<float2*>(&C[(size_t)(row + 8) * DD + col]) = v1;
        }
    }
}

// ---------------------------------------------------------------------------
// Flash attention (fp32, unchanged from R1): one block per (q-tile 64, b*h)
// ---------------------------------------------------------------------------
#define FLASH_SMEM_FLOATS (2 * 128 * 65 + 64 * 65 + 3 * 64)
#define FLASH_SMEM_BYTES  (FLASH_SMEM_FLOATS * 4)

__global__ __launch_bounds__(256, 2) void flash_kernel() {
    extern __shared__ float smf[];
    float* Qt  = smf;
    float* KV  = smf + 128 * 65;
    float* Pt  = smf + 2 * 128 * 65;
    float* m_s  = Pt + 64 * 65;
    float* l_s  = m_s + 64;
    float* al_s = l_s + 64;

    const int tid = threadIdx.x;
    const int q0  = blockIdx.x * 64;
    const int bh  = blockIdx.y;
    const int b   = bh >> 4;
    const int h   = bh & 15;
    const size_t base_bh = (size_t)b * SS * DD + (size_t)h * HD;

#pragma unroll
    for (int rep = 0; rep < 32; rep++) {
        int lin = rep * 256 + tid;
        int r = lin >> 7;
        int d = lin & 127;
        Qt[d * 65 + r] = g_q[base_bh + (size_t)(q0 + r) * DD + d];
    }

    if (tid < 64) { m_s[tid] = -INFINITY; l_s[tid] = 0.f; }

    float oacc[8][4];
#pragma unroll
    for (int a = 0; a < 8; a++)
#pragma unroll
        for (int c = 0; c < 4; c++) oacc[a][c] = 0.f;

    const int ty = tid >> 4, tx = tid & 15;
    const int ry = tid >> 5, cx = tid & 31;

    for (int kv0 = 0; kv0 < SS; kv0 += 64) {
        __syncthreads();

#pragma unroll
        for (int rep = 0; rep < 32; rep++) {
            int lin = rep * 256 + tid;
            int j = lin >> 7;
            int d = lin & 127;
            KV[d * 65 + j] = g_k[base_bh + (size_t)(kv0 + j) * DD + d];
        }
        __syncthreads();

        float sacc[4][4];
#pragma unroll
        for (int a = 0; a < 4; a++)
#pragma unroll
            for (int c = 0; c < 4; c++) sacc[a][c] = 0.f;

#pragma unroll 4
        for (int d = 0; d < 128; d++) {
            float ar[4], br[4];
#pragma unroll
            for (int a = 0; a < 4; a++) ar[a] = Qt[d * 65 + 4 * ty + a];
#pragma unroll
            for (int c = 0; c < 4; c++) br[c] = KV[d * 65 + 4 * tx + c];
#pragma unroll
            for (int a = 0; a < 4; a++)
#pragma unroll
                for (int c = 0; c < 4; c++)
                    sacc[a][c] += ar[a] * br[c];
        }
#pragma unroll
        for (int c = 0; c < 4; c++)
#pragma unroll
            for (int a = 0; a < 4; a++)
                Pt[(4 * tx + c) * 65 + 4 * ty + a] =
                    sacc[a][c] * 0.08838834764831845f;
        __syncthreads();

#pragma unroll
        for (int rep = 0; rep < 8; rep++) {
            int lin4 = rep * 256 + tid;
            int j  = lin4 >> 5;
            int d4 = (lin4 & 31) << 2;
            *reinterpret_cast<float4*>(&KV[j * 128 + d4]) =
                *reinterpret_cast<const float4*>(
                    &g_v[base_bh + (size_t)(kv0 + j) * DD + d4]);
        }

        if (tid < 64) {
            const int r = tid;
            float mi = m_s[r];
            float mx = mi;
#pragma unroll 8
            for (int c = 0; c < 64; c++)
                mx = fmaxf(mx, Pt[c * 65 + r]);
            float alpha = __expf(mi - mx);
            float sum = 0.f;
#pragma unroll 8
            for (int c = 0; c < 64; c++) {
                float p = __expf(Pt[c * 65 + r] - mx);
                Pt[c * 65 + r] = p;
                sum += p;
            }
            m_s[r]  = mx;
            l_s[r]  = l_s[r] * alpha + sum;
            al_s[r] = alpha;
        }
        __syncthreads();

        float al[8];
#pragma unroll
        for (int a = 0; a < 8; a++) al[a] = al_s[ry * 8 + a];
#pragma unroll
        for (int a = 0; a < 8; a++)
#pragma unroll
            for (int c = 0; c < 4; c++) oacc[a][c] *= al[a];

#pragma unroll 2
        for (int j = 0; j < 64; j++) {
            float4 vv = *reinterpret_cast<float4*>(&KV[j * 128 + 4 * cx]);
#pragma unroll
            for (int a = 0; a < 8; a++) {
                float p = Pt[j * 65 + ry * 8 + a];
                oacc[a][0] += p * vv.x;
                oacc[a][1] += p * vv.y;
                oacc[a][2] += p * vv.z;
                oacc[a][3] += p * vv.w;
            }
        }
    }

#pragma unroll
    for (int a = 0; a < 8; a++) {
        float inv = 1.0f / l_s[ry * 8 + a];
        float4 o = make_float4(oacc[a][0] * inv, oacc[a][1] * inv,
                               oacc[a][2] * inv, oacc[a][3] * inv);
        *reinterpret_cast<float4*>(
            &g_ao[base_bh + (size_t)(q0 + ry * 8 + a) * DD + 4 * cx]) = o;
    }
}

// ---------------------------------------------------------------------------
// Launch
// ---------------------------------------------------------------------------
extern "C" void kernel_launch(void* const* d_in, const int* in_sizes, int n_in,
                              void* d_out, int out_size) {
    (void)in_sizes; (void)n_in; (void)out_size;
    const float* x  = (const float*)d_in[0];
    const float* wq = (const float*)d_in[1];
    const float* wk = (const float*)d_in[2];
    const float* wv = (const float*)d_in[3];
    const float* wo = (const float*)d_in[4];
    float* out = (float*)d_out;

    float *q, *k, *v, *ao;
    __nv_bfloat16 *abig, *wbig;
    cudaGetSymbolAddress((void**)&q,    g_q);
    cudaGetSymbolAddress((void**)&k,    g_k);
    cudaGetSymbolAddress((void**)&v,    g_v);
    cudaGetSymbolAddress((void**)&ao,   g_ao);
    cudaGetSymbolAddress((void**)&abig, g_abig);
    cudaGetSymbolAddress((void**)&wbig, g_wbig);

    cudaFuncSetAttribute(gemm_hmma,
                         cudaFuncAttributeMaxDynamicSharedMemorySize,
                         GEMM_SMEM_BYTES);
    cudaFuncSetAttribute(flash_kernel,
                         cudaFuncAttributeMaxDynamicSharedMemorySize,
                         FLASH_SMEM_BYTES);

    const int n_act = BS * DD;
    const int n_w   = DD * DD;
    dim3 ggrid(DD / 128, BS / 128);  // (16, 32)

    rope_table_kernel<<<(SS * NPAIR + 255) / 256, 256>>>();

    split3_kernel<<<(n_act + 255) / 256, 256>>>(x, abig, n_act, 0);

    split3_kernel<<<(n_w + 255) / 256, 256>>>(wq, wbig, n_w, 1);
    gemm_hmma<<<ggrid, 256, GEMM_SMEM_BYTES>>>(abig, wbig, q);
    split3_kernel<<<(n_w + 255) / 256, 256>>>(wk, wbig, n_w, 1);
    gemm_hmma<<<ggrid, 256, GEMM_SMEM_BYTES>>>(abig, wbig, k);
    split3_kernel<<<(n_w + 255) / 256, 256>>>(wv, wbig, n_w, 1);
    gemm_hmma<<<ggrid, 256, GEMM_SMEM_BYTES>>>(abig, wbig, v);

    rope_apply_kernel<<<(BS * (DD / 2) + 255) / 256, 256>>>();

    dim3 fgrid(SS / 64, BB * HH);
    flash_kernel<<<fgrid, 256, FLASH_SMEM_BYTES>>>();

    split3_kernel<<<(n_act + 255) / 256, 256>>>(ao, abig, n_act, 0);
    split3_kernel<<<(n_w + 255) / 256, 256>>>(wo, wbig, n_w, 1);
    gemm_hmma<<<ggrid, 256, GEMM_SMEM_BYTES>>>(abig, wbig, out);
}